// round 12
// baseline (speedup 1.0000x reference)
#include <cuda_runtime.h>
#include <cstdint>

// XSimGCL / LightGCN on GB300 (sm_103a) — compact CSR, base-pair build.
// R12: (a) software-pipelined spmm edge loop (prefetch next indices ->
// break idx->gather L2 dependency chain), (b) scan_partials folded into
// scan_final (each block sums the raw partials before it).

#define NUM_USERS 100000
#define NUM_ITEMS 50000
#define NTOT      (NUM_USERS + NUM_ITEMS)   // 150000
#define D4        16                        // float4s per 64-dim row
#define BATCH     4096
#define MAXE      4200000                   // >= 2*NUM_BASE_EDGES
#define MAXROWS   8192
#define SCAN_B    256
#define NBLK      ((NTOT + SCAN_B - 1) / SCAN_B)   // 586

// Scratch (allocation-free rule: __device__ globals; device-code refs only).
__device__ float4   g_X1[NTOT * D4];
__device__ float4   g_X2[NTOT * D4];
__device__ float4   g_X3[NTOT * D4];
__device__ int      g_cnt[NTOT];
__device__ int      g_off[NTOT + 1];
__device__ int      g_pos[NTOT];
__device__ int      g_part[1024];           // >= NBLK (raw per-block sums)
__device__ int2     g_cva[MAXE];            // packed {col, float_as_int(val)}
__device__ unsigned g_bitmap [(NTOT + 31) / 32];   // flagged (layer-3 outputs)
__device__ unsigned g_bitmap2[(NTOT + 31) / 32];   // flagged ∪ N(flagged)
__device__ int      g_rowlist[MAXROWS];
__device__ int      g_nrows;

// ---------------------------------------------------------------------------
__global__ void zero_kernel() {
    int i = blockIdx.x * blockDim.x + threadIdx.x;
    if (i < NTOT) g_cnt[i] = 0;
    if (i < (NTOT + 31) / 32) { g_bitmap[i] = 0u; g_bitmap2[i] = 0u; }
    if (i == 0) g_nrows = 0;
}

// Fused: degree histogram from BASE pairs + mark flagged rows + compact.
__global__ void degree_mark_kernel(const int* __restrict__ rows,  // u
                                   const int* __restrict__ cols,  // v+NU
                                   const int* __restrict__ uid,
                                   const int* __restrict__ iid,
                                   int nb) {
    int i = blockIdx.x * blockDim.x + threadIdx.x;
    if (i < nb) {
        unsigned u = (unsigned)__ldcs(&rows[i]);
        unsigned w = (unsigned)__ldcs(&cols[i]);
        if (u < NTOT) atomicAdd(&g_cnt[u], 1);
        if (w < NTOT) atomicAdd(&g_cnt[w], 1);
    }
    if (i < BATCH) {
        unsigned r[2];
        r[0] = (unsigned)__ldg(&uid[i]);
        r[1] = (unsigned)__ldg(&iid[i]) + NUM_USERS;
        #pragma unroll
        for (int k = 0; k < 2; k++) {
            if (r[k] < NTOT) {
                unsigned bit = 1u << (r[k] & 31);
                unsigned old = atomicOr(&g_bitmap[r[k] >> 5], bit);
                atomicOr(&g_bitmap2[r[k] >> 5], bit);
                if (!(old & bit)) {
                    int p = atomicAdd(&g_nrows, 1);
                    if (p < MAXROWS) g_rowlist[p] = (int)r[k];
                }
            }
        }
    }
}

// ---------------------------------------------------------------------------
// 2-pass scan: per-block raw sums, then each final block computes its own
// prefix over the partials (no separate partials-scan kernel).
// ---------------------------------------------------------------------------
__global__ void scan_reduce_kernel() {
    __shared__ int sh[SCAN_B];
    int idx = blockIdx.x * SCAN_B + threadIdx.x;
    sh[threadIdx.x] = (idx < NTOT) ? g_cnt[idx] : 0;
    __syncthreads();
    #pragma unroll
    for (int off = SCAN_B / 2; off > 0; off >>= 1) {
        if (threadIdx.x < off) sh[threadIdx.x] += sh[threadIdx.x + off];
        __syncthreads();
    }
    if (threadIdx.x == 0) g_part[blockIdx.x] = sh[0];
}

__global__ void scan_final_kernel() {
    __shared__ int sh[SCAN_B];

    // 1) base = sum of raw partials for blocks before this one
    int part = 0;
    for (int i = threadIdx.x; i < blockIdx.x; i += SCAN_B) part += g_part[i];
    sh[threadIdx.x] = part;
    __syncthreads();
    #pragma unroll
    for (int off = SCAN_B / 2; off > 0; off >>= 1) {
        if (threadIdx.x < off) sh[threadIdx.x] += sh[threadIdx.x + off];
        __syncthreads();
    }
    int base = sh[0];
    __syncthreads();

    // 2) intra-block exclusive scan of g_cnt
    int idx = blockIdx.x * SCAN_B + threadIdx.x;
    int c = (idx < NTOT) ? g_cnt[idx] : 0;
    sh[threadIdx.x] = c;
    __syncthreads();
    #pragma unroll
    for (int off = 1; off < SCAN_B; off <<= 1) {
        int t = (threadIdx.x >= off) ? sh[threadIdx.x - off] : 0;
        __syncthreads();
        sh[threadIdx.x] += t;
        __syncthreads();
    }
    if (idx < NTOT) {
        int off = base + sh[threadIdx.x] - c;   // exclusive
        g_off[idx] = off;
        g_pos[idx] = off;
        if (idx == NTOT - 1) g_off[NTOT] = off + c;
    }
}

// ---------------------------------------------------------------------------
// Scatter BOTH directed edges per base pair; fused bitmap2 marking.
// ---------------------------------------------------------------------------
__global__ void scatter_kernel(const float* __restrict__ vals,
                               const int*   __restrict__ rows,
                               const int*   __restrict__ cols,
                               int nb) {
    int i = blockIdx.x * blockDim.x + threadIdx.x;
    if (i >= nb) return;
    unsigned u = (unsigned)__ldcs(&rows[i]);
    unsigned w = (unsigned)__ldcs(&cols[i]);
    int vbits = __float_as_int(__ldcs(&vals[i]));

    if (u < NTOT) {
        int p = atomicAdd(&g_pos[u], 1);
        if (p < MAXE) __stcs(&g_cva[p], make_int2((int)w, vbits));
        if ((g_bitmap[u >> 5] >> (u & 31)) & 1u)
            if (w < NTOT) atomicOr(&g_bitmap2[w >> 5], 1u << (w & 31));
    }
    if (w < NTOT) {
        int p = atomicAdd(&g_pos[w], 1);
        if (p < MAXE) __stcs(&g_cva[p], make_int2((int)u, vbits));
        if ((g_bitmap[w >> 5] >> (w & 31)) & 1u)
            if (u < NTOT) atomicOr(&g_bitmap2[u >> 5], 1u << (u & 31));
    }
}

// ---------------------------------------------------------------------------
// CSR SpMM, software-pipelined: next iteration's indices prefetched while
// current gathers are consumed -> only one L2 latency exposed per step.
// ---------------------------------------------------------------------------
template <int LAYER>
__device__ __forceinline__ float4 sp_gather(const float4* __restrict__ ue,
                                            const float4* __restrict__ ie,
                                            const float4* __restrict__ src,
                                            int c, int l) {
    if (LAYER == 0)
        return (c < NUM_USERS) ? __ldg(&ue[c * D4 + l])
                               : __ldg(&ie[(c - NUM_USERS) * D4 + l]);
    return __ldg(&src[c * D4 + l]);
}

template <int LAYER>
__global__ void __launch_bounds__(256)
spmm_csr_kernel(const float4* __restrict__ ue,
                const float4* __restrict__ ie) {
    int gid = blockIdx.x * blockDim.x + threadIdx.x;
    int g = gid >> 4;
    int l = gid & 15;

    int r;
    if (LAYER == 2) {
        if (g >= g_nrows) return;
        r = g_rowlist[g];
    } else {
        if (g >= NTOT) return;
        r = g;
        if (LAYER == 1) {
            if (!((g_bitmap2[r >> 5] >> (r & 31)) & 1u)) return;
        }
    }

    int j   = __ldg(&g_off[r]);
    int end = __ldg(&g_off[r + 1]);

    const float4* __restrict__ src = (LAYER == 1) ? g_X1 : g_X2;  // unused L0
    float4 acc = make_float4(0.f, 0.f, 0.f, 0.f);

    if (j + 1 < end) {
        int2 ca = __ldcs(&g_cva[j]);
        int2 cb = __ldcs(&g_cva[j + 1]);
        j += 2;
        for (; j + 1 < end; j += 2) {
            int2 na = __ldcs(&g_cva[j]);        // prefetch next pair
            int2 nb = __ldcs(&g_cva[j + 1]);
            float4 xa = sp_gather<LAYER>(ue, ie, src, ca.x, l);
            float4 xb = sp_gather<LAYER>(ue, ie, src, cb.x, l);
            float va = __int_as_float(ca.y), vb = __int_as_float(cb.y);
            acc.x += va * xa.x + vb * xb.x;
            acc.y += va * xa.y + vb * xb.y;
            acc.z += va * xa.z + vb * xb.z;
            acc.w += va * xa.w + vb * xb.w;
            ca = na; cb = nb;
        }
        {
            float4 xa = sp_gather<LAYER>(ue, ie, src, ca.x, l);
            float4 xb = sp_gather<LAYER>(ue, ie, src, cb.x, l);
            float va = __int_as_float(ca.y), vb = __int_as_float(cb.y);
            acc.x += va * xa.x + vb * xb.x;
            acc.y += va * xa.y + vb * xb.y;
            acc.z += va * xa.z + vb * xb.z;
            acc.w += va * xa.w + vb * xb.w;
        }
    }
    if (j < end) {
        int2 ca = __ldcs(&g_cva[j]);
        float4 xa = sp_gather<LAYER>(ue, ie, src, ca.x, l);
        float va = __int_as_float(ca.y);
        acc.x += va * xa.x; acc.y += va * xa.y;
        acc.z += va * xa.z; acc.w += va * xa.w;
    }

    float4* __restrict__ dst = (LAYER == 0) ? g_X1 : (LAYER == 1) ? g_X2 : g_X3;
    dst[r * D4 + l] = acc;
}

// ---------------------------------------------------------------------------
// Readout: out[b] = dot((X1+X2+X3)[u], (X1+X2+X3)[i+NU]) / 9
// ---------------------------------------------------------------------------
__global__ void dot_kernel(const int* __restrict__ uid,
                           const int* __restrict__ iid,
                           float* __restrict__ out) {
    int gid = blockIdx.x * blockDim.x + threadIdx.x;
    int b = gid >> 4;
    int l = gid & 15;
    if (b >= BATCH) return;

    unsigned ur = (unsigned)__ldg(&uid[b]);
    unsigned ir = (unsigned)__ldg(&iid[b]) + NUM_USERS;
    float d = 0.f;

    if (ur < NTOT && ir < NTOT) {
        int uo = (int)ur * D4 + l;
        int io = (int)ir * D4 + l;
        float4 a1 = g_X1[uo], a2 = g_X2[uo], a3 = g_X3[uo];
        float4 b1 = g_X1[io], b2 = g_X2[io], b3 = g_X3[io];
        float fux = a1.x + a2.x + a3.x, fuy = a1.y + a2.y + a3.y;
        float fuz = a1.z + a2.z + a3.z, fuw = a1.w + a2.w + a3.w;
        float fix = b1.x + b2.x + b3.x, fiy = b1.y + b2.y + b3.y;
        float fiz = b1.z + b2.z + b3.z, fiw = b1.w + b2.w + b3.w;
        d = fux * fix + fuy * fiy + fuz * fiz + fuw * fiw;
    }

    #pragma unroll
    for (int off = 8; off > 0; off >>= 1)
        d += __shfl_down_sync(0xffffffffu, d, off, 16);

    if (l == 0) out[b] = d * (1.0f / 9.0f);
}

// ---------------------------------------------------------------------------
extern "C" void kernel_launch(void* const* d_in, const int* in_sizes, int n_in,
                              void* d_out, int out_size) {
    const float4* user_emb = (const float4*)d_in[0];   // [100000,64] f32
    const float4* item_emb = (const float4*)d_in[1];   // [50000,64]  f32
    const float*  vals     = (const float*) d_in[2];   // [2E] f32
    const int*    rows     = (const int*)   d_in[3];   // [2E] i32: [u, v+NU]
    const int*    cols     = (const int*)   d_in[4];   // [2E] i32: [v+NU, u]
    const int*    uid      = (const int*)   d_in[5];   // [4096] i32
    const int*    iid      = (const int*)   d_in[6];   // [4096] i32
    float*        out      = (float*)d_out;            // [4096] f32

    const int ne = in_sizes[2];
    const int nb = ne / 2;                  // base (undirected) pairs

    zero_kernel<<<(NTOT + 255) / 256, 256>>>();

    int bblocks = (nb + 255) / 256;
    degree_mark_kernel<<<bblocks, 256>>>(rows, cols, uid, iid, nb);
    scan_reduce_kernel<<<NBLK, SCAN_B>>>();
    scan_final_kernel<<<NBLK, SCAN_B>>>();
    scatter_kernel<<<bblocks, 256>>>(vals, rows, cols, nb);

    int t_dense = NTOT * D4;
    spmm_csr_kernel<0><<<(t_dense + 255) / 256, 256>>>(user_emb, item_emb);
    spmm_csr_kernel<1><<<(t_dense + 255) / 256, 256>>>(user_emb, item_emb);
    spmm_csr_kernel<2><<<(MAXROWS * 16 + 255) / 256, 256>>>(user_emb, item_emb);

    dot_kernel<<<(BATCH * 16 + 255) / 256, 256>>>(uid, iid, out);
}

// round 14
// speedup vs baseline: 1.0613x; 1.0613x over previous
#include <cuda_runtime.h>
#include <cstdint>

// XSimGCL / LightGCN on GB300 (sm_103a) — compact CSR, base-pair build.
// R13: consolidation. spmm loop reverted to simple 2-wide (R12 pipelining
// cost ~5us: LTS-BW bound, not latency bound). Kept: folded 2-kernel scan.
// New: g_cva uses default cache policy (read 3x -> L2 reuse is real);
// spmm2 emits final=X1+X2+X3 so dot reads one array.

#define NUM_USERS 100000
#define NUM_ITEMS 50000
#define NTOT      (NUM_USERS + NUM_ITEMS)   // 150000
#define D4        16                        // float4s per 64-dim row
#define BATCH     4096
#define MAXE      4200000                   // >= 2*NUM_BASE_EDGES
#define MAXROWS   8192
#define SCAN_B    256
#define NBLK      ((NTOT + SCAN_B - 1) / SCAN_B)   // 586

// Scratch (allocation-free rule: __device__ globals; device-code refs only).
__device__ float4   g_X1[NTOT * D4];
__device__ float4   g_X2[NTOT * D4];
__device__ float4   g_X3[NTOT * D4];        // holds FINAL (X1+X2+X3) at flagged rows
__device__ int      g_cnt[NTOT];
__device__ int      g_off[NTOT + 1];
__device__ int      g_pos[NTOT];
__device__ int      g_part[1024];           // >= NBLK (raw per-block sums)
__device__ int2     g_cva[MAXE];            // packed {col, float_as_int(val)}
__device__ unsigned g_bitmap [(NTOT + 31) / 32];   // flagged (layer-3 outputs)
__device__ unsigned g_bitmap2[(NTOT + 31) / 32];   // flagged ∪ N(flagged)
__device__ int      g_rowlist[MAXROWS];
__device__ int      g_nrows;

// ---------------------------------------------------------------------------
__global__ void zero_kernel() {
    int i = blockIdx.x * blockDim.x + threadIdx.x;
    if (i < NTOT) g_cnt[i] = 0;
    if (i < (NTOT + 31) / 32) { g_bitmap[i] = 0u; g_bitmap2[i] = 0u; }
    if (i == 0) g_nrows = 0;
}

// Fused: degree histogram from BASE pairs + mark flagged rows + compact.
__global__ void degree_mark_kernel(const int* __restrict__ rows,  // u
                                   const int* __restrict__ cols,  // v+NU
                                   const int* __restrict__ uid,
                                   const int* __restrict__ iid,
                                   int nb) {
    int i = blockIdx.x * blockDim.x + threadIdx.x;
    if (i < nb) {
        unsigned u = (unsigned)__ldcs(&rows[i]);
        unsigned w = (unsigned)__ldcs(&cols[i]);
        if (u < NTOT) atomicAdd(&g_cnt[u], 1);
        if (w < NTOT) atomicAdd(&g_cnt[w], 1);
    }
    if (i < BATCH) {
        unsigned r[2];
        r[0] = (unsigned)__ldg(&uid[i]);
        r[1] = (unsigned)__ldg(&iid[i]) + NUM_USERS;
        #pragma unroll
        for (int k = 0; k < 2; k++) {
            if (r[k] < NTOT) {
                unsigned bit = 1u << (r[k] & 31);
                unsigned old = atomicOr(&g_bitmap[r[k] >> 5], bit);
                atomicOr(&g_bitmap2[r[k] >> 5], bit);
                if (!(old & bit)) {
                    int p = atomicAdd(&g_nrows, 1);
                    if (p < MAXROWS) g_rowlist[p] = (int)r[k];
                }
            }
        }
    }
}

// ---------------------------------------------------------------------------
// 2-pass scan: per-block raw sums, then each final block computes its own
// prefix over the partials (no separate partials-scan kernel).
// ---------------------------------------------------------------------------
__global__ void scan_reduce_kernel() {
    __shared__ int sh[SCAN_B];
    int idx = blockIdx.x * SCAN_B + threadIdx.x;
    sh[threadIdx.x] = (idx < NTOT) ? g_cnt[idx] : 0;
    __syncthreads();
    #pragma unroll
    for (int off = SCAN_B / 2; off > 0; off >>= 1) {
        if (threadIdx.x < off) sh[threadIdx.x] += sh[threadIdx.x + off];
        __syncthreads();
    }
    if (threadIdx.x == 0) g_part[blockIdx.x] = sh[0];
}

__global__ void scan_final_kernel() {
    __shared__ int sh[SCAN_B];

    // 1) base = sum of raw partials for blocks before this one
    int part = 0;
    for (int i = threadIdx.x; i < blockIdx.x; i += SCAN_B) part += g_part[i];
    sh[threadIdx.x] = part;
    __syncthreads();
    #pragma unroll
    for (int off = SCAN_B / 2; off > 0; off >>= 1) {
        if (threadIdx.x < off) sh[threadIdx.x] += sh[threadIdx.x + off];
        __syncthreads();
    }
    int base = sh[0];
    __syncthreads();

    // 2) intra-block exclusive scan of g_cnt
    int idx = blockIdx.x * SCAN_B + threadIdx.x;
    int c = (idx < NTOT) ? g_cnt[idx] : 0;
    sh[threadIdx.x] = c;
    __syncthreads();
    #pragma unroll
    for (int off = 1; off < SCAN_B; off <<= 1) {
        int t = (threadIdx.x >= off) ? sh[threadIdx.x - off] : 0;
        __syncthreads();
        sh[threadIdx.x] += t;
        __syncthreads();
    }
    if (idx < NTOT) {
        int off = base + sh[threadIdx.x] - c;   // exclusive
        g_off[idx] = off;
        g_pos[idx] = off;
        if (idx == NTOT - 1) g_off[NTOT] = off + c;
    }
}

// ---------------------------------------------------------------------------
// Scatter BOTH directed edges per base pair; fused bitmap2 marking.
// Default store policy for g_cva (re-read by all 3 spmm layers -> L2 reuse).
// ---------------------------------------------------------------------------
__global__ void scatter_kernel(const float* __restrict__ vals,
                               const int*   __restrict__ rows,
                               const int*   __restrict__ cols,
                               int nb) {
    int i = blockIdx.x * blockDim.x + threadIdx.x;
    if (i >= nb) return;
    unsigned u = (unsigned)__ldcs(&rows[i]);
    unsigned w = (unsigned)__ldcs(&cols[i]);
    int vbits = __float_as_int(__ldcs(&vals[i]));

    if (u < NTOT) {
        int p = atomicAdd(&g_pos[u], 1);
        if (p < MAXE) g_cva[p] = make_int2((int)w, vbits);
        if ((g_bitmap[u >> 5] >> (u & 31)) & 1u)
            if (w < NTOT) atomicOr(&g_bitmap2[w >> 5], 1u << (w & 31));
    }
    if (w < NTOT) {
        int p = atomicAdd(&g_pos[w], 1);
        if (p < MAXE) g_cva[p] = make_int2((int)u, vbits);
        if ((g_bitmap[w >> 5] >> (w & 31)) & 1u)
            if (u < NTOT) atomicOr(&g_bitmap2[u >> 5], 1u << (u & 31));
    }
}

// ---------------------------------------------------------------------------
// CSR SpMM: one 16-lane group per row, register accumulate, single store.
// LAYER 0: src = (user_emb|item_emb) direct, dst = X1 (all rows)
// LAYER 1: X1 -> X2, only rows in bitmap2 (flagged ∪ N(flagged))
// LAYER 2: X2 -> X3, only g_rowlist; dst value = X1[r]+X2[r]+acc (FINAL)
// ---------------------------------------------------------------------------
template <int LAYER>
__global__ void __launch_bounds__(256)
spmm_csr_kernel(const float4* __restrict__ ue,
                const float4* __restrict__ ie) {
    int gid = blockIdx.x * blockDim.x + threadIdx.x;
    int g = gid >> 4;
    int l = gid & 15;

    int r;
    if (LAYER == 2) {
        if (g >= g_nrows) return;
        r = g_rowlist[g];
    } else {
        if (g >= NTOT) return;
        r = g;
        if (LAYER == 1) {
            if (!((g_bitmap2[r >> 5] >> (r & 31)) & 1u)) return;
        }
    }

    int beg = __ldg(&g_off[r]);
    int end = __ldg(&g_off[r + 1]);

    const float4* __restrict__ src = (LAYER == 1) ? g_X1 : g_X2;  // unused L0
    float4 acc = make_float4(0.f, 0.f, 0.f, 0.f);

    int j = beg;
    for (; j + 1 < end; j += 2) {       // 2 gathers in flight per group
        int2 ca = __ldg(&g_cva[j]);
        int2 cb = __ldg(&g_cva[j + 1]);
        float4 xa, xb;
        if (LAYER == 0) {
            xa = (ca.x < NUM_USERS) ? __ldg(&ue[ca.x * D4 + l])
                                    : __ldg(&ie[(ca.x - NUM_USERS) * D4 + l]);
            xb = (cb.x < NUM_USERS) ? __ldg(&ue[cb.x * D4 + l])
                                    : __ldg(&ie[(cb.x - NUM_USERS) * D4 + l]);
        } else {
            xa = __ldg(&src[ca.x * D4 + l]);
            xb = __ldg(&src[cb.x * D4 + l]);
        }
        float va = __int_as_float(ca.y), vb = __int_as_float(cb.y);
        acc.x += va * xa.x + vb * xb.x;
        acc.y += va * xa.y + vb * xb.y;
        acc.z += va * xa.z + vb * xb.z;
        acc.w += va * xa.w + vb * xb.w;
    }
    if (j < end) {
        int2 ca = __ldg(&g_cva[j]);
        float4 xa;
        if (LAYER == 0) {
            xa = (ca.x < NUM_USERS) ? __ldg(&ue[ca.x * D4 + l])
                                    : __ldg(&ie[(ca.x - NUM_USERS) * D4 + l]);
        } else {
            xa = __ldg(&src[ca.x * D4 + l]);
        }
        float va = __int_as_float(ca.y);
        acc.x += va * xa.x; acc.y += va * xa.y;
        acc.z += va * xa.z; acc.w += va * xa.w;
    }

    if (LAYER == 2) {                     // emit final = X1 + X2 + X3
        float4 a = g_X1[r * D4 + l];
        float4 b = g_X2[r * D4 + l];
        acc.x += a.x + b.x; acc.y += a.y + b.y;
        acc.z += a.z + b.z; acc.w += a.w + b.w;
    }

    float4* __restrict__ dst = (LAYER == 0) ? g_X1 : (LAYER == 1) ? g_X2 : g_X3;
    dst[r * D4 + l] = acc;
}

// ---------------------------------------------------------------------------
// Readout: out[b] = dot(final[u], final[i+NU]) / 9   (final precomputed in X3)
// ---------------------------------------------------------------------------
__global__ void dot_kernel(const int* __restrict__ uid,
                           const int* __restrict__ iid,
                           float* __restrict__ out) {
    int gid = blockIdx.x * blockDim.x + threadIdx.x;
    int b = gid >> 4;
    int l = gid & 15;
    if (b >= BATCH) return;

    unsigned ur = (unsigned)__ldg(&uid[b]);
    unsigned ir = (unsigned)__ldg(&iid[b]) + NUM_USERS;
    float d = 0.f;

    if (ur < NTOT && ir < NTOT) {
        float4 a = g_X3[(int)ur * D4 + l];
        float4 c = g_X3[(int)ir * D4 + l];
        d = a.x * c.x + a.y * c.y + a.z * c.z + a.w * c.w;
    }

    #pragma unroll
    for (int off = 8; off > 0; off >>= 1)
        d += __shfl_down_sync(0xffffffffu, d, off, 16);

    if (l == 0) out[b] = d * (1.0f / 9.0f);
}

// ---------------------------------------------------------------------------
extern "C" void kernel_launch(void* const* d_in, const int* in_sizes, int n_in,
                              void* d_out, int out_size) {
    const float4* user_emb = (const float4*)d_in[0];   // [100000,64] f32
    const float4* item_emb = (const float4*)d_in[1];   // [50000,64]  f32
    const float*  vals     = (const float*) d_in[2];   // [2E] f32
    const int*    rows     = (const int*)   d_in[3];   // [2E] i32: [u, v+NU]
    const int*    cols     = (const int*)   d_in[4];   // [2E] i32: [v+NU, u]
    const int*    uid      = (const int*)   d_in[5];   // [4096] i32
    const int*    iid      = (const int*)   d_in[6];   // [4096] i32
    float*        out      = (float*)d_out;            // [4096] f32

    const int ne = in_sizes[2];
    const int nb = ne / 2;                  // base (undirected) pairs

    zero_kernel<<<(NTOT + 255) / 256, 256>>>();

    int bblocks = (nb + 255) / 256;
    degree_mark_kernel<<<bblocks, 256>>>(rows, cols, uid, iid, nb);
    scan_reduce_kernel<<<NBLK, SCAN_B>>>();
    scan_final_kernel<<<NBLK, SCAN_B>>>();
    scatter_kernel<<<bblocks, 256>>>(vals, rows, cols, nb);

    int t_dense = NTOT * D4;
    spmm_csr_kernel<0><<<(t_dense + 255) / 256, 256>>>(user_emb, item_emb);
    spmm_csr_kernel<1><<<(t_dense + 255) / 256, 256>>>(user_emb, item_emb);
    spmm_csr_kernel<2><<<(MAXROWS * 16 + 255) / 256, 256>>>(user_emb, item_emb);

    dot_kernel<<<(BATCH * 16 + 255) / 256, 256>>>(uid, iid, out);
}